// round 13
// baseline (speedup 1.0000x reference)
#include <cuda_runtime.h>
#include <cuda_bf16.h>
#include <cstdint>

#define NN  131072   // nodes
#define EE  524288   // edges
#define VV  32000    // vocab
#define DIN 256
#define DD  128
#define SP  136      // padded smem row stride (bf16 elems): conflict-free ldmatrix

// ---------------- device scratch (no allocations allowed) ----------------
__device__ float g_t3[(size_t)VV * DD];           // embed @ Wc^T + bc
__device__ __nv_bfloat16 g_h1h[(size_t)NN * DD];  // h1 hi (pre-split)
__device__ __nv_bfloat16 g_h1l[(size_t)NN * DD];  // h1 lo
__device__ float g_xb[(size_t)NN * DD];           // y2 = h1 @ W2^T
__device__ float g_wc[DD * DIN];                  // Wc = W1 @ Wn
__device__ float g_bc[DD];                        // bc = W1 @ bn
__device__ int   g_cnt[NN];    // invariant: zero at call entry (re-zeroed in scan23)
__device__ int   g_fill[NN];   // invariant: zero before k_scatter (re-zeroed in scan23)
__device__ float g_dinv[NN];
__device__ int   g_rowptr[NN + 1];
__device__ int   g_bsum[128];
__device__ int   g_col[EE];

// ---------------- weight fold: Wc = W1 @ Wn,  bc = W1 @ bn ----------------
__global__ void k_combine(const float* __restrict__ w1, const float* __restrict__ wn,
                          const float* __restrict__ bn) {
    __shared__ float row[DD];
    int i = blockIdx.x;
    int j = threadIdx.x;
    if (j < DD) row[j] = w1[i * DD + j];
    __syncthreads();
    float acc = 0.f;
#pragma unroll 8
    for (int k = 0; k < DD; ++k) acc += row[k] * wn[k * DIN + j];
    g_wc[i * DIN + j] = acc;
    if (j == 0) {
        float b = 0.f;
        for (int k = 0; k < DD; ++k) b += row[k] * bn[k];
        g_bc[i] = b;
    }
}

// ---------------- CSR build ----------------
__global__ void k_hist(const int2* __restrict__ dst2) {   // 2 edges / thread
    int e2 = blockIdx.x * blockDim.x + threadIdx.x;
    if (e2 < EE / 2) {
        int2 d = dst2[e2];
        atomicAdd(&g_cnt[d.x], 1);
        atomicAdd(&g_cnt[d.y], 1);
    }
}
__global__ void k_scan1() {
    __shared__ int sh[1024];
    int tid = threadIdx.x;
    int i = blockIdx.x * 1024 + tid;
    int v = g_cnt[i];
    int x = v;
    sh[tid] = x; __syncthreads();
    for (int off = 1; off < 1024; off <<= 1) {
        int y = (tid >= off) ? sh[tid - off] : 0;
        __syncthreads();
        x += y; sh[tid] = x; __syncthreads();
    }
    g_rowptr[i] = x - v;
    if (tid == 1023) g_bsum[blockIdx.x] = x;
}
// block-offset apply + dinv + self-clean cnt/fill + tail outputs (merged)
__global__ void k_scan23(const int* __restrict__ tok, float* __restrict__ out, size_t osz) {
    __shared__ int sb[128];
    int t = threadIdx.x;
    int i = blockIdx.x * 256 + t;
    if (t < 128) sb[t] = g_bsum[t];
    __syncthreads();
    for (int off = 1; off < 128; off <<= 1) {   // inclusive scan, 7 steps
        int v = 0;
        if (t < 128 && t >= off) v = sb[t - off];
        __syncthreads();
        if (t < 128) sb[t] += v;
        __syncthreads();
    }
    int grp = i >> 10;
    int off = (grp == 0) ? 0 : sb[grp - 1];
    g_rowptr[i] += off;
    g_dinv[i] = rsqrtf((float)(g_cnt[i] + 1));
    g_cnt[i]  = 0;
    g_fill[i] = 0;
    if (i == 0) g_rowptr[NN] = EE;
    size_t base = (size_t)NN * DD;
    size_t ii = (size_t)i;
    if (base + (size_t)NN <= osz)     out[base + ii] = (float)tok[i];
    if (base + 2 * (size_t)NN <= osz) out[base + NN + ii] = 1.0f;
    if (base + 3 * (size_t)NN <= osz) out[base + 2 * (size_t)NN + ii] = (float)(i & 2047);
}
__global__ void k_scatter(const int* __restrict__ src, const int* __restrict__ dst) {
    int e = blockIdx.x * blockDim.x + threadIdx.x;
    if (e < EE) {
        int d = dst[e];
        int p = g_rowptr[d] + atomicAdd(&g_fill[d], 1);
        g_col[p] = src[e];
    }
}

// ---------------- layer-1 agg (chunked): h1 = relu(aggnorm(T3[tok]) + b1) -> split bf16 ----------------
__global__ void k_agg0(const int* __restrict__ tok, const float* __restrict__ t3,
                       const float* __restrict__ b1, int base) {
    int gw   = base + ((blockIdx.x * blockDim.x + threadIdx.x) >> 5);
    int lane = threadIdx.x & 31;
    int beg = g_rowptr[gw], end = g_rowptr[gw + 1];
    float di = g_dinv[gw];
    const float4* x4 = (const float4*)t3;
    float4 v = x4[(size_t)tok[gw] * 32 + lane];
    float s = di * di;
    float ax = v.x * s, ay = v.y * s, az = v.z * s, aw = v.w * s;
    for (int j = beg; j < end; ++j) {
        int   sc = g_col[j];
        float w  = g_dinv[sc] * di;
        float4 u = x4[(size_t)tok[sc] * 32 + lane];
        ax += w * u.x; ay += w * u.y; az += w * u.z; aw += w * u.w;
    }
    float4 b = ((const float4*)b1)[lane];
    float ox = fmaxf(ax + b.x, 0.f), oy = fmaxf(ay + b.y, 0.f);
    float oz = fmaxf(az + b.z, 0.f), ow = fmaxf(aw + b.w, 0.f);
    __nv_bfloat16 hx = __float2bfloat16(ox), hy = __float2bfloat16(oy);
    __nv_bfloat16 hz = __float2bfloat16(oz), hw = __float2bfloat16(ow);
    __nv_bfloat16 lx = __float2bfloat16(ox - __bfloat162float(hx));
    __nv_bfloat16 ly = __float2bfloat16(oy - __bfloat162float(hy));
    __nv_bfloat16 lz = __float2bfloat16(oz - __bfloat162float(hz));
    __nv_bfloat16 lw = __float2bfloat16(ow - __bfloat162float(hw));
    size_t o2 = (size_t)gw * 64 + lane * 2;
    ((__nv_bfloat162*)g_h1h)[o2]     = __halves2bfloat162(hx, hy);
    ((__nv_bfloat162*)g_h1h)[o2 + 1] = __halves2bfloat162(hz, hw);
    ((__nv_bfloat162*)g_h1l)[o2]     = __halves2bfloat162(lx, ly);
    ((__nv_bfloat162*)g_h1l)[o2 + 1] = __halves2bfloat162(lz, lw);
}

// ---------------- layer-2 aggregation: out = aggnorm(y2) + b2 ----------------
__global__ void k_agg2(const float* __restrict__ x, const float* __restrict__ b2,
                       float* __restrict__ outp) {
    int gw   = (blockIdx.x * blockDim.x + threadIdx.x) >> 5;
    int lane = threadIdx.x & 31;
    if (gw >= NN) return;
    int beg = g_rowptr[gw], end = g_rowptr[gw + 1];
    float di = g_dinv[gw];
    const float4* x4 = (const float4*)x;
    float4 v = x4[(size_t)gw * 32 + lane];
    float s = di * di;
    float ax = v.x * s, ay = v.y * s, az = v.z * s, aw = v.w * s;
    for (int j = beg; j < end; ++j) {
        int   sc = g_col[j];
        float w  = g_dinv[sc] * di;
        float4 u = x4[(size_t)sc * 32 + lane];
        ax += w * u.x; ay += w * u.y; az += w * u.z; aw += w * u.w;
    }
    float4 b = ((const float4*)b2)[lane];
    ((float4*)outp)[(size_t)gw * 32 + lane] =
        make_float4(ax + b.x, ay + b.y, az + b.z, aw + b.w);
}

// ---------------- HMMA helpers ----------------
__device__ __forceinline__ void split_store(char* hi, char* lo, int row, int c4, float4 f) {
    __nv_bfloat16 hx = __float2bfloat16(f.x), hy = __float2bfloat16(f.y);
    __nv_bfloat16 hz = __float2bfloat16(f.z), hw = __float2bfloat16(f.w);
    __nv_bfloat16 lx = __float2bfloat16(f.x - __bfloat162float(hx));
    __nv_bfloat16 ly = __float2bfloat16(f.y - __bfloat162float(hy));
    __nv_bfloat16 lz = __float2bfloat16(f.z - __bfloat162float(hz));
    __nv_bfloat16 lw = __float2bfloat16(f.w - __bfloat162float(hw));
    size_t off = ((size_t)row * SP + c4) * 2;
    *(__nv_bfloat162*)(hi + off)     = __halves2bfloat162(hx, hy);
    *(__nv_bfloat162*)(hi + off + 4) = __halves2bfloat162(hz, hw);
    *(__nv_bfloat162*)(lo + off)     = __halves2bfloat162(lx, ly);
    *(__nv_bfloat162*)(lo + off + 4) = __halves2bfloat162(lz, lw);
}
__device__ __forceinline__ void ldsm4(uint32_t& r0, uint32_t& r1, uint32_t& r2, uint32_t& r3,
                                      uint32_t addr) {
    asm volatile("ldmatrix.sync.aligned.m8n8.x4.shared.b16 {%0,%1,%2,%3}, [%4];"
                 : "=r"(r0), "=r"(r1), "=r"(r2), "=r"(r3) : "r"(addr));
}
__device__ __forceinline__ void mma16816(float* c, const uint32_t* a, const uint32_t* b) {
    asm volatile(
        "mma.sync.aligned.m16n8k16.row.col.f32.bf16.bf16.f32 "
        "{%0,%1,%2,%3}, {%4,%5,%6,%7}, {%8,%9}, {%0,%1,%2,%3};"
        : "+f"(c[0]), "+f"(c[1]), "+f"(c[2]), "+f"(c[3])
        : "r"(a[0]), "r"(a[1]), "r"(a[2]), "r"(a[3]), "r"(b[0]), "r"(b[1]));
}

#define A64_TILE  (64  * SP * 2)   // 17408
#define W128_TILE (128 * SP * 2)   // 34816
#define SMEM_G (2 * A64_TILE + 2 * W128_TILE)   // 104448 -> 2 CTAs/SM

// ---------------- vocab GEMM: 64-row tiles, 2 CTAs/SM, fp32 A split in-kernel ----------------
__global__ void __launch_bounds__(256, 2) k_mma_v(
    const float* __restrict__ A, const float* __restrict__ W,
    const float* __restrict__ bias, float* __restrict__ C, int Mtiles)
{
    extern __shared__ char smem[];
    char* sAh = smem;
    char* sAl = smem + A64_TILE;
    char* sWh = smem + 2 * A64_TILE;
    char* sWl = smem + 2 * A64_TILE + W128_TILE;
    const uint32_t uAh = (uint32_t)__cvta_generic_to_shared(sAh);
    const uint32_t uAl = (uint32_t)__cvta_generic_to_shared(sAl);
    const uint32_t uWh = (uint32_t)__cvta_generic_to_shared(sWh);
    const uint32_t uWl = (uint32_t)__cvta_generic_to_shared(sWl);

    const int t = threadIdx.x;
    const int L = t & 31;
    const int wid = t >> 5;
    const int wm = wid >> 2, wn = wid & 3;
    const int aRow  = wm * 32 + (L & 15);
    const int aHalf = (L >> 4) * 8;
    const int bRow  = wn * 32 + ((L >> 4) & 1) * 8 + (L & 7);
    const int bCol  = ((L >> 3) & 1) * 8;

    float c[2][4][4];
    for (int tile = blockIdx.x; tile < Mtiles; tile += gridDim.x) {
        const size_t m0 = (size_t)tile * 64;
#pragma unroll
        for (int i = 0; i < 2; i++)
#pragma unroll
            for (int j = 0; j < 4; j++) {
                c[i][j][0] = 0.f; c[i][j][1] = 0.f; c[i][j][2] = 0.f; c[i][j][3] = 0.f;
            }

        for (int kb = 0; kb < DIN; kb += 128) {
            __syncthreads();
#pragma unroll
            for (int it = 0; it < 8; ++it) {
                int slot = it * 256 + t;
                int row = slot >> 5, c4 = (slot & 31) << 2;
                split_store(sAh, sAl, row, c4,
                            *(const float4*)(A + (m0 + row) * DIN + kb + c4));
            }
#pragma unroll
            for (int it = 0; it < 16; ++it) {
                int slot = it * 256 + t;
                int row = slot >> 5, c4 = (slot & 31) << 2;
                split_store(sWh, sWl, row, c4,
                            *(const float4*)(W + (size_t)row * DIN + kb + c4));
            }
            __syncthreads();

#pragma unroll
            for (int ks = 0; ks < 8; ++ks) {
                const int k0 = ks * 16;
                uint32_t ah[2][4], al[2][4], bh[2][4], bl[2][4];
#pragma unroll
                for (int mt = 0; mt < 2; ++mt) {
                    uint32_t off = (uint32_t)(((aRow + mt * 16) * SP + k0 + aHalf) * 2);
                    ldsm4(ah[mt][0], ah[mt][1], ah[mt][2], ah[mt][3], uAh + off);
                    ldsm4(al[mt][0], al[mt][1], al[mt][2], al[mt][3], uAl + off);
                }
#pragma unroll
                for (int p = 0; p < 2; ++p) {
                    uint32_t off = (uint32_t)(((bRow + p * 16) * SP + k0 + bCol) * 2);
                    ldsm4(bh[p][0], bh[p][1], bh[p][2], bh[p][3], uWh + off);
                    ldsm4(bl[p][0], bl[p][1], bl[p][2], bl[p][3], uWl + off);
                }
#pragma unroll
                for (int mt = 0; mt < 2; ++mt)
#pragma unroll
                    for (int nt = 0; nt < 4; ++nt) {
                        const uint32_t bfh[2] = { bh[nt >> 1][(nt & 1) * 2],
                                                  bh[nt >> 1][(nt & 1) * 2 + 1] };
                        const uint32_t bfl[2] = { bl[nt >> 1][(nt & 1) * 2],
                                                  bl[nt >> 1][(nt & 1) * 2 + 1] };
                        mma16816(c[mt][nt], ah[mt], bfh);
                        mma16816(c[mt][nt], ah[mt], bfl);
                        mma16816(c[mt][nt], al[mt], bfh);
                    }
            }
        }

        const int lrow = L >> 2, lcol = (L & 3) * 2;
#pragma unroll
        for (int nt = 0; nt < 4; ++nt) {
            const int col = wn * 32 + nt * 8 + lcol;
            float b0 = __ldg(bias + col), b1 = __ldg(bias + col + 1);
#pragma unroll
            for (int mt = 0; mt < 2; ++mt) {
                size_t r0 = m0 + wm * 32 + mt * 16 + lrow;
                *(float2*)(C + r0 * DD + col) =
                    make_float2(c[mt][nt][0] + b0, c[mt][nt][1] + b1);
                *(float2*)(C + (r0 + 8) * DD + col) =
                    make_float2(c[mt][nt][2] + b0, c[mt][nt][3] + b1);
            }
        }
    }
}

// ---------------- layer-2 GEMM (tile-ranged): A pre-split bf16, 2 CTAs/SM ----------------
__global__ void __launch_bounds__(256, 2) k_mma2b(
    const __nv_bfloat16* __restrict__ Ah, const __nv_bfloat16* __restrict__ Al,
    const float* __restrict__ W, float* __restrict__ C, int tileOff, int tileEnd)
{
    extern __shared__ char smem[];
    char* sAh = smem;
    char* sAl = smem + A64_TILE;
    char* sWh = smem + 2 * A64_TILE;
    char* sWl = smem + 2 * A64_TILE + W128_TILE;
    const uint32_t uAh = (uint32_t)__cvta_generic_to_shared(sAh);
    const uint32_t uAl = (uint32_t)__cvta_generic_to_shared(sAl);
    const uint32_t uWh = (uint32_t)__cvta_generic_to_shared(sWh);
    const uint32_t uWl = (uint32_t)__cvta_generic_to_shared(sWl);

    const int t = threadIdx.x;
    const int L = t & 31;
    const int wid = t >> 5;
    const int wm = wid >> 2, wn = wid & 3;
    const int aRow  = wm * 32 + (L & 15);
    const int aHalf = (L >> 4) * 8;
    const int bRow  = wn * 32 + ((L >> 4) & 1) * 8 + (L & 7);
    const int bCol  = ((L >> 3) & 1) * 8;

    // W2 resident: split once
#pragma unroll
    for (int it = 0; it < 16; ++it) {
        int slot = it * 256 + t;
        int row = slot >> 5, c4 = (slot & 31) << 2;
        split_store(sWh, sWl, row, c4, *(const float4*)(W + (size_t)row * DD + c4));
    }

    float c[2][4][4];
    for (int tile = tileOff + blockIdx.x; tile < tileEnd; tile += gridDim.x) {
        const size_t m0 = (size_t)tile * 64;
        __syncthreads();
#pragma unroll
        for (int it = 0; it < 8; ++it) {
            int slot = it * 256 + t;            // 0..2047
            int arr  = slot >> 10;              // 0=hi, 1=lo
            int row  = (slot >> 4) & 63;
            int c8   = slot & 15;
            const __nv_bfloat16* g = (arr ? Al : Ah) + (m0 + row) * DD + c8 * 8;
            char* dstBase = arr ? sAl : sAh;
            *(uint4*)(dstBase + (row * SP + c8 * 8) * 2) = *(const uint4*)g;
        }
        __syncthreads();

#pragma unroll
        for (int i = 0; i < 2; i++)
#pragma unroll
            for (int j = 0; j < 4; j++) {
                c[i][j][0] = 0.f; c[i][j][1] = 0.f; c[i][j][2] = 0.f; c[i][j][3] = 0.f;
            }
#pragma unroll
        for (int ks = 0; ks < 8; ++ks) {
            const int k0 = ks * 16;
            uint32_t ah[2][4], al[2][4], bh[2][4], bl[2][4];
#pragma unroll
            for (int mt = 0; mt < 2; ++mt) {
                uint32_t off = (uint32_t)(((aRow + mt * 16) * SP + k0 + aHalf) * 2);
                ldsm4(ah[mt][0], ah[mt][1], ah[mt][2], ah[mt][3], uAh + off);
                ldsm4(al[mt][0], al[mt][1], al[mt][2], al[mt][3], uAl + off);
            }
#pragma unroll
            for (int p = 0; p < 2; ++p) {
                uint32_t off = (uint32_t)(((bRow + p * 16) * SP + k0 + bCol) * 2);
                ldsm4(bh[p][0], bh[p][1], bh[p][2], bh[p][3], uWh + off);
                ldsm4(bl[p][0], bl[p][1], bl[p][2], bl[p][3], uWl + off);
            }
#pragma unroll
            for (int mt = 0; mt < 2; ++mt)
#pragma unroll
                for (int nt = 0; nt < 4; ++nt) {
                    const uint32_t bfh[2] = { bh[nt >> 1][(nt & 1) * 2],
                                              bh[nt >> 1][(nt & 1) * 2 + 1] };
                    const uint32_t bfl[2] = { bl[nt >> 1][(nt & 1) * 2],
                                              bl[nt >> 1][(nt & 1) * 2 + 1] };
                    mma16816(c[mt][nt], ah[mt], bfh);
                    mma16816(c[mt][nt], ah[mt], bfl);
                    mma16816(c[mt][nt], al[mt], bfh);
                }
        }

        const int lrow = L >> 2, lcol = (L & 3) * 2;
#pragma unroll
        for (int nt = 0; nt < 4; ++nt) {
            const int col = wn * 32 + nt * 8 + lcol;
#pragma unroll
            for (int mt = 0; mt < 2; ++mt) {
                size_t r0 = m0 + wm * 32 + mt * 16 + lrow;
                *(float2*)(C + r0 * DD + col)       = make_float2(c[mt][nt][0], c[mt][nt][1]);
                *(float2*)(C + (r0 + 8) * DD + col) = make_float2(c[mt][nt][2], c[mt][nt][3]);
            }
        }
    }
}

// ---------------- launch ----------------
extern "C" void kernel_launch(void* const* d_in, const int* in_sizes, int n_in,
                              void* d_out, int out_size) {
    const int*   tok = (const int*)d_in[0];
    const int*   ei  = (const int*)d_in[1];
    const float* emb = (const float*)d_in[2];
    const float* wn  = (const float*)d_in[3];
    const float* bn  = (const float*)d_in[4];
    const float* w1  = (const float*)d_in[5];
    const float* b1  = (const float*)d_in[6];
    const float* w2  = (const float*)d_in[7];
    const float* b2  = (const float*)d_in[8];
    float* out = (float*)d_out;

    const int* src = ei;
    const int* dst = ei + EE;

    float *t3p, *xbp, *wcp, *bcp;
    __nv_bfloat16 *h1hp, *h1lp;
    cudaGetSymbolAddress((void**)&t3p,  g_t3);
    cudaGetSymbolAddress((void**)&xbp,  g_xb);
    cudaGetSymbolAddress((void**)&wcp,  g_wc);
    cudaGetSymbolAddress((void**)&bcp,  g_bc);
    cudaGetSymbolAddress((void**)&h1hp, g_h1h);
    cudaGetSymbolAddress((void**)&h1lp, g_h1l);

    cudaFuncSetAttribute(k_mma_v, cudaFuncAttributeMaxDynamicSharedMemorySize, SMEM_G);
    cudaFuncSetAttribute(k_mma2b, cudaFuncAttributeMaxDynamicSharedMemorySize, SMEM_G);

    // streams + events (created once; resources, not device memory)
    static cudaStream_t s2 = nullptr;
    static cudaEvent_t  evF = nullptr, evJ = nullptr, evA0 = nullptr, evA1 = nullptr,
                        evM = nullptr;
    if (s2 == nullptr) {
        cudaStreamCreateWithFlags(&s2, cudaStreamNonBlocking);
        cudaEventCreateWithFlags(&evF,  cudaEventDisableTiming);
        cudaEventCreateWithFlags(&evJ,  cudaEventDisableTiming);
        cudaEventCreateWithFlags(&evA0, cudaEventDisableTiming);
        cudaEventCreateWithFlags(&evA1, cudaEventDisableTiming);
        cudaEventCreateWithFlags(&evM,  cudaEventDisableTiming);
    }

    // ---- fork: CSR build (+merged tail outputs) on s2 ----
    cudaEventRecord(evF, 0);
    cudaStreamWaitEvent(s2, evF, 0);

    k_hist   <<<EE / 512, 256, 0, s2>>>((const int2*)dst);
    k_scan1  <<<NN / 1024, 1024, 0, s2>>>();
    k_scan23 <<<NN / 256, 256, 0, s2>>>(tok, out, (size_t)out_size);
    k_scatter<<<EE / 256, 256, 0, s2>>>(src, dst);
    cudaEventRecord(evJ, s2);

    // ---- main stream: fold weights + vocab GEMM (independent of CSR) ----
    k_combine<<<DD, DIN>>>(w1, wn, bn);
    k_mma_v<<<296, 256, SMEM_G>>>(emb, wcp, bcp, t3p, VV / 64);

    // ---- join CSR into main ----
    cudaStreamWaitEvent(0, evJ, 0);

    // ---- 2-chunk pipeline: agg0(c0) -> {mma2b(c0) on s2 || agg0(c1) on main} -> mma2b(c1) ----
    const int halfN = NN / 2;            // 65536 nodes
    const int halfT = (NN / 64) / 2;     // 1024 tiles

    k_agg0<<<(halfN * 32) / 256, 256>>>(tok, t3p, b1, 0);
    cudaEventRecord(evA0, 0);
    cudaStreamWaitEvent(s2, evA0, 0);
    k_mma2b<<<296, 256, SMEM_G, s2>>>(h1hp, h1lp, w2, xbp, 0, halfT);

    k_agg0<<<(halfN * 32) / 256, 256>>>(tok, t3p, b1, halfN);
    cudaEventRecord(evA1, 0);
    cudaStreamWaitEvent(s2, evA1, 0);
    k_mma2b<<<296, 256, SMEM_G, s2>>>(h1hp, h1lp, w2, xbp, halfT, 2 * halfT);
    cudaEventRecord(evM, s2);

    // ---- join, final aggregation -> output ----
    cudaStreamWaitEvent(0, evM, 0);
    k_agg2<<<(NN * 32) / 256, 256>>>(xbp, b2, out);
}

// round 14
// speedup vs baseline: 1.0324x; 1.0324x over previous
#include <cuda_runtime.h>
#include <cuda_bf16.h>
#include <cstdint>

#define NN  131072   // nodes
#define EE  524288   // edges
#define VV  32000    // vocab
#define DIN 256
#define DD  128
#define SP  136      // padded smem row stride (bf16 elems): conflict-free ldmatrix

// ---------------- device scratch (no allocations allowed) ----------------
__device__ float g_t3[(size_t)VV * DD];           // embed @ Wc^T + bc
__device__ __nv_bfloat16 g_h1h[(size_t)NN * DD];  // h1 hi (pre-split)
__device__ __nv_bfloat16 g_h1l[(size_t)NN * DD];  // h1 lo
__device__ float g_xb[(size_t)NN * DD];           // y2 = h1 @ W2^T
__device__ float g_wc[DD * DIN];                  // Wc = W1 @ Wn
__device__ float g_bc[DD];                        // bc = W1 @ bn
__device__ int   g_cnt[NN];    // invariant: zero at call entry (re-zeroed in scan23)
__device__ int   g_fill[NN];   // invariant: zero before k_scatter (re-zeroed in scan23)
__device__ float g_dinv[NN];
__device__ int   g_rowptr[NN + 1];
__device__ int   g_bsum[128];
__device__ int   g_col[EE];

// ---------------- weight fold: Wc = W1 @ Wn,  bc = W1 @ bn ----------------
__global__ void k_combine(const float* __restrict__ w1, const float* __restrict__ wn,
                          const float* __restrict__ bn) {
    __shared__ float row[DD];
    int i = blockIdx.x;
    int j = threadIdx.x;
    if (j < DD) row[j] = w1[i * DD + j];
    __syncthreads();
    float acc = 0.f;
#pragma unroll 8
    for (int k = 0; k < DD; ++k) acc += row[k] * wn[k * DIN + j];
    g_wc[i * DIN + j] = acc;
    if (j == 0) {
        float b = 0.f;
        for (int k = 0; k < DD; ++k) b += row[k] * bn[k];
        g_bc[i] = b;
    }
}

// ---------------- CSR build ----------------
__global__ void k_hist(const int2* __restrict__ dst2) {   // 2 edges / thread
    int e2 = blockIdx.x * blockDim.x + threadIdx.x;
    if (e2 < EE / 2) {
        int2 d = dst2[e2];
        atomicAdd(&g_cnt[d.x], 1);
        atomicAdd(&g_cnt[d.y], 1);
    }
}
// warp-shuffle scan: 1024 threads, 2 syncs (vs 20)
__global__ void k_scan1() {
    __shared__ int wsum[32];
    int tid = threadIdx.x;
    int i = blockIdx.x * 1024 + tid;
    int lane = tid & 31, w = tid >> 5;
    int v = g_cnt[i];
    int x = v;
#pragma unroll
    for (int off = 1; off < 32; off <<= 1) {
        int y = __shfl_up_sync(0xFFFFFFFFu, x, off);
        if (lane >= off) x += y;
    }
    if (lane == 31) wsum[w] = x;
    __syncthreads();
    if (w == 0) {
        int s = wsum[lane];
#pragma unroll
        for (int off = 1; off < 32; off <<= 1) {
            int y = __shfl_up_sync(0xFFFFFFFFu, s, off);
            if (lane >= off) s += y;
        }
        wsum[lane] = s;
    }
    __syncthreads();
    int base = (w == 0) ? 0 : wsum[w - 1];
    g_rowptr[i] = base + x - v;          // exclusive
    if (tid == 1023) g_bsum[blockIdx.x] = base + x;   // block total
}
// block-offset apply + dinv + self-clean cnt/fill + tail outputs (merged)
__global__ void k_scan23(const int* __restrict__ tok, float* __restrict__ out, size_t osz) {
    __shared__ int sb[128];
    int t = threadIdx.x;
    int i = blockIdx.x * 256 + t;
    if (t < 128) sb[t] = g_bsum[t];
    __syncthreads();
    for (int off = 1; off < 128; off <<= 1) {   // inclusive scan, 7 steps
        int v = 0;
        if (t < 128 && t >= off) v = sb[t - off];
        __syncthreads();
        if (t < 128) sb[t] += v;
        __syncthreads();
    }
    int grp = i >> 10;
    int off = (grp == 0) ? 0 : sb[grp - 1];
    g_rowptr[i] += off;
    g_dinv[i] = rsqrtf((float)(g_cnt[i] + 1));
    g_cnt[i]  = 0;
    g_fill[i] = 0;
    if (i == 0) g_rowptr[NN] = EE;
    size_t base = (size_t)NN * DD;
    size_t ii = (size_t)i;
    if (base + (size_t)NN <= osz)     out[base + ii] = (float)tok[i];
    if (base + 2 * (size_t)NN <= osz) out[base + NN + ii] = 1.0f;
    if (base + 3 * (size_t)NN <= osz) out[base + 2 * (size_t)NN + ii] = (float)(i & 2047);
}
__global__ void k_scatter(const int2* __restrict__ src2, const int2* __restrict__ dst2) {
    int e2 = blockIdx.x * blockDim.x + threadIdx.x;
    if (e2 < EE / 2) {
        int2 d = dst2[e2];
        int2 s = src2[e2];
        int p0 = g_rowptr[d.x] + atomicAdd(&g_fill[d.x], 1);
        int p1 = g_rowptr[d.y] + atomicAdd(&g_fill[d.y], 1);
        g_col[p0] = s.x;
        g_col[p1] = s.y;
    }
}

// ---------------- layer-1 agg: h1 = relu(aggnorm(T3[tok]) + b1) -> split bf16 ----------------
__global__ void k_agg0(const int* __restrict__ tok, const float* __restrict__ t3,
                       const float* __restrict__ b1) {
    int gw   = (blockIdx.x * blockDim.x + threadIdx.x) >> 5;
    int lane = threadIdx.x & 31;
    if (gw >= NN) return;
    int beg = g_rowptr[gw], end = g_rowptr[gw + 1];
    float di = g_dinv[gw];
    const float4* x4 = (const float4*)t3;
    float4 v = x4[(size_t)tok[gw] * 32 + lane];
    float s = di * di;
    float ax = v.x * s, ay = v.y * s, az = v.z * s, aw = v.w * s;
    for (int j = beg; j < end; ++j) {
        int   sc = g_col[j];
        float w  = g_dinv[sc] * di;
        float4 u = x4[(size_t)tok[sc] * 32 + lane];
        ax += w * u.x; ay += w * u.y; az += w * u.z; aw += w * u.w;
    }
    float4 b = ((const float4*)b1)[lane];
    float ox = fmaxf(ax + b.x, 0.f), oy = fmaxf(ay + b.y, 0.f);
    float oz = fmaxf(az + b.z, 0.f), ow = fmaxf(aw + b.w, 0.f);
    __nv_bfloat16 hx = __float2bfloat16(ox), hy = __float2bfloat16(oy);
    __nv_bfloat16 hz = __float2bfloat16(oz), hw = __float2bfloat16(ow);
    __nv_bfloat16 lx = __float2bfloat16(ox - __bfloat162float(hx));
    __nv_bfloat16 ly = __float2bfloat16(oy - __bfloat162float(hy));
    __nv_bfloat16 lz = __float2bfloat16(oz - __bfloat162float(hz));
    __nv_bfloat16 lw = __float2bfloat16(ow - __bfloat162float(hw));
    size_t o2 = (size_t)gw * 64 + lane * 2;
    ((__nv_bfloat162*)g_h1h)[o2]     = __halves2bfloat162(hx, hy);
    ((__nv_bfloat162*)g_h1h)[o2 + 1] = __halves2bfloat162(hz, hw);
    ((__nv_bfloat162*)g_h1l)[o2]     = __halves2bfloat162(lx, ly);
    ((__nv_bfloat162*)g_h1l)[o2 + 1] = __halves2bfloat162(lz, lw);
}

// ---------------- layer-2 aggregation: out = aggnorm(y2) + b2 ----------------
__global__ void k_agg2(const float* __restrict__ x, const float* __restrict__ b2,
                       float* __restrict__ outp) {
    int gw   = (blockIdx.x * blockDim.x + threadIdx.x) >> 5;
    int lane = threadIdx.x & 31;
    if (gw >= NN) return;
    int beg = g_rowptr[gw], end = g_rowptr[gw + 1];
    float di = g_dinv[gw];
    const float4* x4 = (const float4*)x;
    float4 v = x4[(size_t)gw * 32 + lane];
    float s = di * di;
    float ax = v.x * s, ay = v.y * s, az = v.z * s, aw = v.w * s;
    for (int j = beg; j < end; ++j) {
        int   sc = g_col[j];
        float w  = g_dinv[sc] * di;
        float4 u = x4[(size_t)sc * 32 + lane];
        ax += w * u.x; ay += w * u.y; az += w * u.z; aw += w * u.w;
    }
    float4 b = ((const float4*)b2)[lane];
    ((float4*)outp)[(size_t)gw * 32 + lane] =
        make_float4(ax + b.x, ay + b.y, az + b.z, aw + b.w);
}

// ---------------- HMMA helpers ----------------
__device__ __forceinline__ void split_store(char* hi, char* lo, int row, int c4, float4 f) {
    __nv_bfloat16 hx = __float2bfloat16(f.x), hy = __float2bfloat16(f.y);
    __nv_bfloat16 hz = __float2bfloat16(f.z), hw = __float2bfloat16(f.w);
    __nv_bfloat16 lx = __float2bfloat16(f.x - __bfloat162float(hx));
    __nv_bfloat16 ly = __float2bfloat16(f.y - __bfloat162float(hy));
    __nv_bfloat16 lz = __float2bfloat16(f.z - __bfloat162float(hz));
    __nv_bfloat16 lw = __float2bfloat16(f.w - __bfloat162float(hw));
    size_t off = ((size_t)row * SP + c4) * 2;
    *(__nv_bfloat162*)(hi + off)     = __halves2bfloat162(hx, hy);
    *(__nv_bfloat162*)(hi + off + 4) = __halves2bfloat162(hz, hw);
    *(__nv_bfloat162*)(lo + off)     = __halves2bfloat162(lx, ly);
    *(__nv_bfloat162*)(lo + off + 4) = __halves2bfloat162(lz, lw);
}
__device__ __forceinline__ void ldsm4(uint32_t& r0, uint32_t& r1, uint32_t& r2, uint32_t& r3,
                                      uint32_t addr) {
    asm volatile("ldmatrix.sync.aligned.m8n8.x4.shared.b16 {%0,%1,%2,%3}, [%4];"
                 : "=r"(r0), "=r"(r1), "=r"(r2), "=r"(r3) : "r"(addr));
}
__device__ __forceinline__ void mma16816(float* c, const uint32_t* a, const uint32_t* b) {
    asm volatile(
        "mma.sync.aligned.m16n8k16.row.col.f32.bf16.bf16.f32 "
        "{%0,%1,%2,%3}, {%4,%5,%6,%7}, {%8,%9}, {%0,%1,%2,%3};"
        : "+f"(c[0]), "+f"(c[1]), "+f"(c[2]), "+f"(c[3])
        : "r"(a[0]), "r"(a[1]), "r"(a[2]), "r"(a[3]), "r"(b[0]), "r"(b[1]));
}

#define A64_TILE  (64  * SP * 2)   // 17408
#define W128_TILE (128 * SP * 2)   // 34816
#define SMEM_G (2 * A64_TILE + 2 * W128_TILE)   // 104448 -> 2 CTAs/SM

// ---------------- vocab GEMM: 64-row tiles, 2 CTAs/SM, fp32 A split in-kernel ----------------
__global__ void __launch_bounds__(256, 2) k_mma_v(
    const float* __restrict__ A, const float* __restrict__ W,
    const float* __restrict__ bias, float* __restrict__ C, int Mtiles)
{
    extern __shared__ char smem[];
    char* sAh = smem;
    char* sAl = smem + A64_TILE;
    char* sWh = smem + 2 * A64_TILE;
    char* sWl = smem + 2 * A64_TILE + W128_TILE;
    const uint32_t uAh = (uint32_t)__cvta_generic_to_shared(sAh);
    const uint32_t uAl = (uint32_t)__cvta_generic_to_shared(sAl);
    const uint32_t uWh = (uint32_t)__cvta_generic_to_shared(sWh);
    const uint32_t uWl = (uint32_t)__cvta_generic_to_shared(sWl);

    const int t = threadIdx.x;
    const int L = t & 31;
    const int wid = t >> 5;
    const int wm = wid >> 2, wn = wid & 3;
    const int aRow  = wm * 32 + (L & 15);
    const int aHalf = (L >> 4) * 8;
    const int bRow  = wn * 32 + ((L >> 4) & 1) * 8 + (L & 7);
    const int bCol  = ((L >> 3) & 1) * 8;

    float c[2][4][4];
    for (int tile = blockIdx.x; tile < Mtiles; tile += gridDim.x) {
        const size_t m0 = (size_t)tile * 64;
#pragma unroll
        for (int i = 0; i < 2; i++)
#pragma unroll
            for (int j = 0; j < 4; j++) {
                c[i][j][0] = 0.f; c[i][j][1] = 0.f; c[i][j][2] = 0.f; c[i][j][3] = 0.f;
            }

        for (int kb = 0; kb < DIN; kb += 128) {
            __syncthreads();
#pragma unroll
            for (int it = 0; it < 8; ++it) {
                int slot = it * 256 + t;
                int row = slot >> 5, c4 = (slot & 31) << 2;
                split_store(sAh, sAl, row, c4,
                            *(const float4*)(A + (m0 + row) * DIN + kb + c4));
            }
#pragma unroll
            for (int it = 0; it < 16; ++it) {
                int slot = it * 256 + t;
                int row = slot >> 5, c4 = (slot & 31) << 2;
                split_store(sWh, sWl, row, c4,
                            *(const float4*)(W + (size_t)row * DIN + kb + c4));
            }
            __syncthreads();

#pragma unroll
            for (int ks = 0; ks < 8; ++ks) {
                const int k0 = ks * 16;
                uint32_t ah[2][4], al[2][4], bh[2][4], bl[2][4];
#pragma unroll
                for (int mt = 0; mt < 2; ++mt) {
                    uint32_t off = (uint32_t)(((aRow + mt * 16) * SP + k0 + aHalf) * 2);
                    ldsm4(ah[mt][0], ah[mt][1], ah[mt][2], ah[mt][3], uAh + off);
                    ldsm4(al[mt][0], al[mt][1], al[mt][2], al[mt][3], uAl + off);
                }
#pragma unroll
                for (int p = 0; p < 2; ++p) {
                    uint32_t off = (uint32_t)(((bRow + p * 16) * SP + k0 + bCol) * 2);
                    ldsm4(bh[p][0], bh[p][1], bh[p][2], bh[p][3], uWh + off);
                    ldsm4(bl[p][0], bl[p][1], bl[p][2], bl[p][3], uWl + off);
                }
#pragma unroll
                for (int mt = 0; mt < 2; ++mt)
#pragma unroll
                    for (int nt = 0; nt < 4; ++nt) {
                        const uint32_t bfh[2] = { bh[nt >> 1][(nt & 1) * 2],
                                                  bh[nt >> 1][(nt & 1) * 2 + 1] };
                        const uint32_t bfl[2] = { bl[nt >> 1][(nt & 1) * 2],
                                                  bl[nt >> 1][(nt & 1) * 2 + 1] };
                        mma16816(c[mt][nt], ah[mt], bfh);
                        mma16816(c[mt][nt], ah[mt], bfl);
                        mma16816(c[mt][nt], al[mt], bfh);
                    }
            }
        }

        const int lrow = L >> 2, lcol = (L & 3) * 2;
#pragma unroll
        for (int nt = 0; nt < 4; ++nt) {
            const int col = wn * 32 + nt * 8 + lcol;
            float b0 = __ldg(bias + col), b1 = __ldg(bias + col + 1);
#pragma unroll
            for (int mt = 0; mt < 2; ++mt) {
                size_t r0 = m0 + wm * 32 + mt * 16 + lrow;
                *(float2*)(C + r0 * DD + col) =
                    make_float2(c[mt][nt][0] + b0, c[mt][nt][1] + b1);
                *(float2*)(C + (r0 + 8) * DD + col) =
                    make_float2(c[mt][nt][2] + b0, c[mt][nt][3] + b1);
            }
        }
    }
}

// ---------------- layer-2 GEMM: A pre-split bf16, 64-row tiles, 2 CTAs/SM ----------------
__global__ void __launch_bounds__(256, 2) k_mma2b(
    const __nv_bfloat16* __restrict__ Ah, const __nv_bfloat16* __restrict__ Al,
    const float* __restrict__ W, float* __restrict__ C, int Mtiles)
{
    extern __shared__ char smem[];
    char* sAh = smem;
    char* sAl = smem + A64_TILE;
    char* sWh = smem + 2 * A64_TILE;
    char* sWl = smem + 2 * A64_TILE + W128_TILE;
    const uint32_t uAh = (uint32_t)__cvta_generic_to_shared(sAh);
    const uint32_t uAl = (uint32_t)__cvta_generic_to_shared(sAl);
    const uint32_t uWh = (uint32_t)__cvta_generic_to_shared(sWh);
    const uint32_t uWl = (uint32_t)__cvta_generic_to_shared(sWl);

    const int t = threadIdx.x;
    const int L = t & 31;
    const int wid = t >> 5;
    const int wm = wid >> 2, wn = wid & 3;
    const int aRow  = wm * 32 + (L & 15);
    const int aHalf = (L >> 4) * 8;
    const int bRow  = wn * 32 + ((L >> 4) & 1) * 8 + (L & 7);
    const int bCol  = ((L >> 3) & 1) * 8;

    // W2 resident: split once
#pragma unroll
    for (int it = 0; it < 16; ++it) {
        int slot = it * 256 + t;
        int row = slot >> 5, c4 = (slot & 31) << 2;
        split_store(sWh, sWl, row, c4, *(const float4*)(W + (size_t)row * DD + c4));
    }

    float c[2][4][4];
    for (int tile = blockIdx.x; tile < Mtiles; tile += gridDim.x) {
        const size_t m0 = (size_t)tile * 64;
        __syncthreads();
#pragma unroll
        for (int it = 0; it < 8; ++it) {
            int slot = it * 256 + t;            // 0..2047
            int arr  = slot >> 10;              // 0=hi, 1=lo
            int row  = (slot >> 4) & 63;
            int c8   = slot & 15;
            const __nv_bfloat16* g = (arr ? Al : Ah) + (m0 + row) * DD + c8 * 8;
            char* dstBase = arr ? sAl : sAh;
            *(uint4*)(dstBase + (row * SP + c8 * 8) * 2) = *(const uint4*)g;
        }
        __syncthreads();

#pragma unroll
        for (int i = 0; i < 2; i++)
#pragma unroll
            for (int j = 0; j < 4; j++) {
                c[i][j][0] = 0.f; c[i][j][1] = 0.f; c[i][j][2] = 0.f; c[i][j][3] = 0.f;
            }
#pragma unroll
        for (int ks = 0; ks < 8; ++ks) {
            const int k0 = ks * 16;
            uint32_t ah[2][4], al[2][4], bh[2][4], bl[2][4];
#pragma unroll
            for (int mt = 0; mt < 2; ++mt) {
                uint32_t off = (uint32_t)(((aRow + mt * 16) * SP + k0 + aHalf) * 2);
                ldsm4(ah[mt][0], ah[mt][1], ah[mt][2], ah[mt][3], uAh + off);
                ldsm4(al[mt][0], al[mt][1], al[mt][2], al[mt][3], uAl + off);
            }
#pragma unroll
            for (int p = 0; p < 2; ++p) {
                uint32_t off = (uint32_t)(((bRow + p * 16) * SP + k0 + bCol) * 2);
                ldsm4(bh[p][0], bh[p][1], bh[p][2], bh[p][3], uWh + off);
                ldsm4(bl[p][0], bl[p][1], bl[p][2], bl[p][3], uWl + off);
            }
#pragma unroll
            for (int mt = 0; mt < 2; ++mt)
#pragma unroll
                for (int nt = 0; nt < 4; ++nt) {
                    const uint32_t bfh[2] = { bh[nt >> 1][(nt & 1) * 2],
                                              bh[nt >> 1][(nt & 1) * 2 + 1] };
                    const uint32_t bfl[2] = { bl[nt >> 1][(nt & 1) * 2],
                                              bl[nt >> 1][(nt & 1) * 2 + 1] };
                    mma16816(c[mt][nt], ah[mt], bfh);
                    mma16816(c[mt][nt], ah[mt], bfl);
                    mma16816(c[mt][nt], al[mt], bfh);
                }
        }

        const int lrow = L >> 2, lcol = (L & 3) * 2;
#pragma unroll
        for (int nt = 0; nt < 4; ++nt) {
            const int col = wn * 32 + nt * 8 + lcol;
#pragma unroll
            for (int mt = 0; mt < 2; ++mt) {
                size_t r0 = m0 + wm * 32 + mt * 16 + lrow;
                *(float2*)(C + r0 * DD + col)       = make_float2(c[mt][nt][0], c[mt][nt][1]);
                *(float2*)(C + (r0 + 8) * DD + col) = make_float2(c[mt][nt][2], c[mt][nt][3]);
            }
        }
    }
}

// ---------------- launch ----------------
extern "C" void kernel_launch(void* const* d_in, const int* in_sizes, int n_in,
                              void* d_out, int out_size) {
    const int*   tok = (const int*)d_in[0];
    const int*   ei  = (const int*)d_in[1];
    const float* emb = (const float*)d_in[2];
    const float* wn  = (const float*)d_in[3];
    const float* bn  = (const float*)d_in[4];
    const float* w1  = (const float*)d_in[5];
    const float* b1  = (const float*)d_in[6];
    const float* w2  = (const float*)d_in[7];
    const float* b2  = (const float*)d_in[8];
    float* out = (float*)d_out;

    const int* src = ei;
    const int* dst = ei + EE;

    float *t3p, *xbp, *wcp, *bcp;
    __nv_bfloat16 *h1hp, *h1lp;
    cudaGetSymbolAddress((void**)&t3p,  g_t3);
    cudaGetSymbolAddress((void**)&xbp,  g_xb);
    cudaGetSymbolAddress((void**)&wcp,  g_wc);
    cudaGetSymbolAddress((void**)&bcp,  g_bc);
    cudaGetSymbolAddress((void**)&h1hp, g_h1h);
    cudaGetSymbolAddress((void**)&h1lp, g_h1l);

    cudaFuncSetAttribute(k_mma_v, cudaFuncAttributeMaxDynamicSharedMemorySize, SMEM_G);
    cudaFuncSetAttribute(k_mma2b, cudaFuncAttributeMaxDynamicSharedMemorySize, SMEM_G);

    // side stream + fork/join events (created once; resources, not device memory)
    static cudaStream_t s2 = nullptr;
    static cudaEvent_t  evF = nullptr, evJ = nullptr;
    if (s2 == nullptr) {
        cudaStreamCreateWithFlags(&s2, cudaStreamNonBlocking);
        cudaEventCreateWithFlags(&evF, cudaEventDisableTiming);
        cudaEventCreateWithFlags(&evJ, cudaEventDisableTiming);
    }

    // ---- fork: CSR build (+merged tail outputs) on s2 ----
    cudaEventRecord(evF, 0);
    cudaStreamWaitEvent(s2, evF, 0);

    k_hist   <<<EE / 512, 256, 0, s2>>>((const int2*)dst);
    k_scan1  <<<NN / 1024, 1024, 0, s2>>>();
    k_scan23 <<<NN / 256, 256, 0, s2>>>(tok, out, (size_t)out_size);
    k_scatter<<<EE / 512, 256, 0, s2>>>((const int2*)src, (const int2*)dst);
    cudaEventRecord(evJ, s2);

    // ---- main stream: fold weights + vocab GEMM (independent of CSR) ----
    k_combine<<<DD, DIN>>>(w1, wn, bn);
    k_mma_v<<<296, 256, SMEM_G>>>(emb, wcp, bcp, t3p, VV / 64);

    // ---- join, then serial node-space chain ----
    cudaStreamWaitEvent(0, evJ, 0);

    k_agg0<<<(NN * 32) / 256, 256>>>(tok, t3p, b1);
    k_mma2b<<<296, 256, SMEM_G>>>(h1hp, h1lp, w2, xbp, NN / 64);
    k_agg2<<<(NN * 32) / 256, 256>>>(xbp, b2, out);
}

// round 15
// speedup vs baseline: 1.0448x; 1.0119x over previous
#include <cuda_runtime.h>
#include <cuda_bf16.h>
#include <cstdint>

#define NN  131072   // nodes
#define EE  524288   // edges
#define VV  32000    // vocab
#define DIN 256
#define DD  128
#define SP  136      // padded smem row stride (bf16 elems): conflict-free ldmatrix

// ---------------- device scratch (no allocations allowed) ----------------
__device__ float g_t3[(size_t)VV * DD];           // embed @ Wc^T + bc
__device__ __nv_bfloat16 g_h1h[(size_t)NN * DD];  // h1 hi (pre-split)
__device__ __nv_bfloat16 g_h1l[(size_t)NN * DD];  // h1 lo
__device__ float g_xb[(size_t)NN * DD];           // y2 = h1 @ W2^T
__device__ float g_wc[DD * DIN];                  // Wc = W1 @ Wn
__device__ float g_bc[DD];                        // bc = W1 @ bn
__device__ int   g_cnt[NN];    // invariant: zero at call entry (re-zeroed in scan23)
__device__ float g_dinv[NN];
__device__ int   g_rowptr[NN + 1];
__device__ int   g_bsum[128];
__device__ int   g_col[EE];
__device__ int   g_slot[EE];   // per-edge slot within its dst row (captured in hist)

// ---------------- weight fold: Wc = W1 @ Wn,  bc = W1 @ bn ----------------
__global__ void k_combine(const float* __restrict__ w1, const float* __restrict__ wn,
                          const float* __restrict__ bn) {
    __shared__ float row[DD];
    int i = blockIdx.x;
    int j = threadIdx.x;
    if (j < DD) row[j] = w1[i * DD + j];
    __syncthreads();
    float acc = 0.f;
#pragma unroll 8
    for (int k = 0; k < DD; ++k) acc += row[k] * wn[k * DIN + j];
    g_wc[i * DIN + j] = acc;
    if (j == 0) {
        float b = 0.f;
        for (int k = 0; k < DD; ++k) b += row[k] * bn[k];
        g_bc[i] = b;
    }
}

// ---------------- CSR build ----------------
// hist also captures each edge's slot (atomicAdd return value) -> coalesced store
__global__ void k_hist(const int2* __restrict__ dst2) {   // 2 edges / thread
    int e2 = blockIdx.x * blockDim.x + threadIdx.x;
    if (e2 < EE / 2) {
        int2 d = dst2[e2];
        int s0 = atomicAdd(&g_cnt[d.x], 1);
        int s1 = atomicAdd(&g_cnt[d.y], 1);
        ((int2*)g_slot)[e2] = make_int2(s0, s1);
    }
}
// warp-shuffle scan: 1024 threads, 2 syncs
__global__ void k_scan1() {
    __shared__ int wsum[32];
    int tid = threadIdx.x;
    int i = blockIdx.x * 1024 + tid;
    int lane = tid & 31, w = tid >> 5;
    int v = g_cnt[i];
    int x = v;
#pragma unroll
    for (int off = 1; off < 32; off <<= 1) {
        int y = __shfl_up_sync(0xFFFFFFFFu, x, off);
        if (lane >= off) x += y;
    }
    if (lane == 31) wsum[w] = x;
    __syncthreads();
    if (w == 0) {
        int s = wsum[lane];
#pragma unroll
        for (int off = 1; off < 32; off <<= 1) {
            int y = __shfl_up_sync(0xFFFFFFFFu, s, off);
            if (lane >= off) s += y;
        }
        wsum[lane] = s;
    }
    __syncthreads();
    int base = (w == 0) ? 0 : wsum[w - 1];
    g_rowptr[i] = base + x - v;          // exclusive
    if (tid == 1023) g_bsum[blockIdx.x] = base + x;   // block total
}
// block-offset apply + dinv + self-clean cnt + tail outputs (merged)
__global__ void k_scan23(const int* __restrict__ tok, float* __restrict__ out, size_t osz) {
    __shared__ int sb[128];
    int t = threadIdx.x;
    int i = blockIdx.x * 256 + t;
    if (t < 128) sb[t] = g_bsum[t];
    __syncthreads();
    for (int off = 1; off < 128; off <<= 1) {   // inclusive scan, 7 steps
        int v = 0;
        if (t < 128 && t >= off) v = sb[t - off];
        __syncthreads();
        if (t < 128) sb[t] += v;
        __syncthreads();
    }
    int grp = i >> 10;
    int off = (grp == 0) ? 0 : sb[grp - 1];
    g_rowptr[i] += off;
    g_dinv[i] = rsqrtf((float)(g_cnt[i] + 1));
    g_cnt[i]  = 0;   // restore invariant for next call's k_hist
    if (i == 0) g_rowptr[NN] = EE;
    size_t base = (size_t)NN * DD;
    size_t ii = (size_t)i;
    if (base + (size_t)NN <= osz)     out[base + ii] = (float)tok[i];
    if (base + 2 * (size_t)NN <= osz) out[base + NN + ii] = 1.0f;
    if (base + 3 * (size_t)NN <= osz) out[base + 2 * (size_t)NN + ii] = (float)(i & 2047);
}
// atomic-free scatter: slot was captured in hist
__global__ void k_scatter(const int2* __restrict__ src2, const int2* __restrict__ dst2) {
    int e2 = blockIdx.x * blockDim.x + threadIdx.x;
    if (e2 < EE / 2) {
        int2 d = dst2[e2];
        int2 s = src2[e2];
        int2 sl = ((const int2*)g_slot)[e2];
        g_col[g_rowptr[d.x] + sl.x] = s.x;
        g_col[g_rowptr[d.y] + sl.y] = s.y;
    }
}

// ---------------- layer-1 agg: h1 = relu(aggnorm(T3[tok]) + b1) -> split bf16 ----------------
__global__ void k_agg0(const int* __restrict__ tok, const float* __restrict__ t3,
                       const float* __restrict__ b1) {
    int gw   = (blockIdx.x * blockDim.x + threadIdx.x) >> 5;
    int lane = threadIdx.x & 31;
    if (gw >= NN) return;
    int beg = g_rowptr[gw], end = g_rowptr[gw + 1];
    float di = g_dinv[gw];
    const float4* x4 = (const float4*)t3;
    float4 v = x4[(size_t)tok[gw] * 32 + lane];
    float s = di * di;
    float ax = v.x * s, ay = v.y * s, az = v.z * s, aw = v.w * s;
    for (int j = beg; j < end; ++j) {
        int   sc = g_col[j];
        float w  = g_dinv[sc] * di;
        float4 u = x4[(size_t)tok[sc] * 32 + lane];
        ax += w * u.x; ay += w * u.y; az += w * u.z; aw += w * u.w;
    }
    float4 b = ((const float4*)b1)[lane];
    float ox = fmaxf(ax + b.x, 0.f), oy = fmaxf(ay + b.y, 0.f);
    float oz = fmaxf(az + b.z, 0.f), ow = fmaxf(aw + b.w, 0.f);
    __nv_bfloat16 hx = __float2bfloat16(ox), hy = __float2bfloat16(oy);
    __nv_bfloat16 hz = __float2bfloat16(oz), hw = __float2bfloat16(ow);
    __nv_bfloat16 lx = __float2bfloat16(ox - __bfloat162float(hx));
    __nv_bfloat16 ly = __float2bfloat16(oy - __bfloat162float(hy));
    __nv_bfloat16 lz = __float2bfloat16(oz - __bfloat162float(hz));
    __nv_bfloat16 lw = __float2bfloat16(ow - __bfloat162float(hw));
    size_t o2 = (size_t)gw * 64 + lane * 2;
    ((__nv_bfloat162*)g_h1h)[o2]     = __halves2bfloat162(hx, hy);
    ((__nv_bfloat162*)g_h1h)[o2 + 1] = __halves2bfloat162(hz, hw);
    ((__nv_bfloat162*)g_h1l)[o2]     = __halves2bfloat162(lx, ly);
    ((__nv_bfloat162*)g_h1l)[o2 + 1] = __halves2bfloat162(lz, lw);
}

// ---------------- layer-2 aggregation: out = aggnorm(y2) + b2 ----------------
__global__ void k_agg2(const float* __restrict__ x, const float* __restrict__ b2,
                       float* __restrict__ outp) {
    int gw   = (blockIdx.x * blockDim.x + threadIdx.x) >> 5;
    int lane = threadIdx.x & 31;
    if (gw >= NN) return;
    int beg = g_rowptr[gw], end = g_rowptr[gw + 1];
    float di = g_dinv[gw];
    const float4* x4 = (const float4*)x;
    float4 v = x4[(size_t)gw * 32 + lane];
    float s = di * di;
    float ax = v.x * s, ay = v.y * s, az = v.z * s, aw = v.w * s;
    for (int j = beg; j < end; ++j) {
        int   sc = g_col[j];
        float w  = g_dinv[sc] * di;
        float4 u = x4[(size_t)sc * 32 + lane];
        ax += w * u.x; ay += w * u.y; az += w * u.z; aw += w * u.w;
    }
    float4 b = ((const float4*)b2)[lane];
    ((float4*)outp)[(size_t)gw * 32 + lane] =
        make_float4(ax + b.x, ay + b.y, az + b.z, aw + b.w);
}

// ---------------- HMMA helpers ----------------
__device__ __forceinline__ void split_store(char* hi, char* lo, int row, int c4, float4 f) {
    __nv_bfloat16 hx = __float2bfloat16(f.x), hy = __float2bfloat16(f.y);
    __nv_bfloat16 hz = __float2bfloat16(f.z), hw = __float2bfloat16(f.w);
    __nv_bfloat16 lx = __float2bfloat16(f.x - __bfloat162float(hx));
    __nv_bfloat16 ly = __float2bfloat16(f.y - __bfloat162float(hy));
    __nv_bfloat16 lz = __float2bfloat16(f.z - __bfloat162float(hz));
    __nv_bfloat16 lw = __float2bfloat16(f.w - __bfloat162float(hw));
    size_t off = ((size_t)row * SP + c4) * 2;
    *(__nv_bfloat162*)(hi + off)     = __halves2bfloat162(hx, hy);
    *(__nv_bfloat162*)(hi + off + 4) = __halves2bfloat162(hz, hw);
    *(__nv_bfloat162*)(lo + off)     = __halves2bfloat162(lx, ly);
    *(__nv_bfloat162*)(lo + off + 4) = __halves2bfloat162(lz, lw);
}
__device__ __forceinline__ void ldsm4(uint32_t& r0, uint32_t& r1, uint32_t& r2, uint32_t& r3,
                                      uint32_t addr) {
    asm volatile("ldmatrix.sync.aligned.m8n8.x4.shared.b16 {%0,%1,%2,%3}, [%4];"
                 : "=r"(r0), "=r"(r1), "=r"(r2), "=r"(r3) : "r"(addr));
}
__device__ __forceinline__ void mma16816(float* c, const uint32_t* a, const uint32_t* b) {
    asm volatile(
        "mma.sync.aligned.m16n8k16.row.col.f32.bf16.bf16.f32 "
        "{%0,%1,%2,%3}, {%4,%5,%6,%7}, {%8,%9}, {%0,%1,%2,%3};"
        : "+f"(c[0]), "+f"(c[1]), "+f"(c[2]), "+f"(c[3])
        : "r"(a[0]), "r"(a[1]), "r"(a[2]), "r"(a[3]), "r"(b[0]), "r"(b[1]));
}

#define A64_TILE  (64  * SP * 2)   // 17408
#define W128_TILE (128 * SP * 2)   // 34816
#define SMEM_G (2 * A64_TILE + 2 * W128_TILE)   // 104448 -> 2 CTAs/SM

// ---------------- vocab GEMM: 64-row tiles, 2 CTAs/SM, fp32 A split in-kernel ----------------
__global__ void __launch_bounds__(256, 2) k_mma_v(
    const float* __restrict__ A, const float* __restrict__ W,
    const float* __restrict__ bias, float* __restrict__ C, int Mtiles)
{
    extern __shared__ char smem[];
    char* sAh = smem;
    char* sAl = smem + A64_TILE;
    char* sWh = smem + 2 * A64_TILE;
    char* sWl = smem + 2 * A64_TILE + W128_TILE;
    const uint32_t uAh = (uint32_t)__cvta_generic_to_shared(sAh);
    const uint32_t uAl = (uint32_t)__cvta_generic_to_shared(sAl);
    const uint32_t uWh = (uint32_t)__cvta_generic_to_shared(sWh);
    const uint32_t uWl = (uint32_t)__cvta_generic_to_shared(sWl);

    const int t = threadIdx.x;
    const int L = t & 31;
    const int wid = t >> 5;
    const int wm = wid >> 2, wn = wid & 3;
    const int aRow  = wm * 32 + (L & 15);
    const int aHalf = (L >> 4) * 8;
    const int bRow  = wn * 32 + ((L >> 4) & 1) * 8 + (L & 7);
    const int bCol  = ((L >> 3) & 1) * 8;

    float c[2][4][4];
    for (int tile = blockIdx.x; tile < Mtiles; tile += gridDim.x) {
        const size_t m0 = (size_t)tile * 64;
#pragma unroll
        for (int i = 0; i < 2; i++)
#pragma unroll
            for (int j = 0; j < 4; j++) {
                c[i][j][0] = 0.f; c[i][j][1] = 0.f; c[i][j][2] = 0.f; c[i][j][3] = 0.f;
            }

        for (int kb = 0; kb < DIN; kb += 128) {
            __syncthreads();
#pragma unroll
            for (int it = 0; it < 8; ++it) {
                int slot = it * 256 + t;
                int row = slot >> 5, c4 = (slot & 31) << 2;
                split_store(sAh, sAl, row, c4,
                            *(const float4*)(A + (m0 + row) * DIN + kb + c4));
            }
#pragma unroll
            for (int it = 0; it < 16; ++it) {
                int slot = it * 256 + t;
                int row = slot >> 5, c4 = (slot & 31) << 2;
                split_store(sWh, sWl, row, c4,
                            *(const float4*)(W + (size_t)row * DIN + kb + c4));
            }
            __syncthreads();

#pragma unroll
            for (int ks = 0; ks < 8; ++ks) {
                const int k0 = ks * 16;
                uint32_t ah[2][4], al[2][4], bh[2][4], bl[2][4];
#pragma unroll
                for (int mt = 0; mt < 2; ++mt) {
                    uint32_t off = (uint32_t)(((aRow + mt * 16) * SP + k0 + aHalf) * 2);
                    ldsm4(ah[mt][0], ah[mt][1], ah[mt][2], ah[mt][3], uAh + off);
                    ldsm4(al[mt][0], al[mt][1], al[mt][2], al[mt][3], uAl + off);
                }
#pragma unroll
                for (int p = 0; p < 2; ++p) {
                    uint32_t off = (uint32_t)(((bRow + p * 16) * SP + k0 + bCol) * 2);
                    ldsm4(bh[p][0], bh[p][1], bh[p][2], bh[p][3], uWh + off);
                    ldsm4(bl[p][0], bl[p][1], bl[p][2], bl[p][3], uWl + off);
                }
#pragma unroll
                for (int mt = 0; mt < 2; ++mt)
#pragma unroll
                    for (int nt = 0; nt < 4; ++nt) {
                        const uint32_t bfh[2] = { bh[nt >> 1][(nt & 1) * 2],
                                                  bh[nt >> 1][(nt & 1) * 2 + 1] };
                        const uint32_t bfl[2] = { bl[nt >> 1][(nt & 1) * 2],
                                                  bl[nt >> 1][(nt & 1) * 2 + 1] };
                        mma16816(c[mt][nt], ah[mt], bfh);
                        mma16816(c[mt][nt], ah[mt], bfl);
                        mma16816(c[mt][nt], al[mt], bfh);
                    }
            }
        }

        const int lrow = L >> 2, lcol = (L & 3) * 2;
#pragma unroll
        for (int nt = 0; nt < 4; ++nt) {
            const int col = wn * 32 + nt * 8 + lcol;
            float b0 = __ldg(bias + col), b1 = __ldg(bias + col + 1);
#pragma unroll
            for (int mt = 0; mt < 2; ++mt) {
                size_t r0 = m0 + wm * 32 + mt * 16 + lrow;
                *(float2*)(C + r0 * DD + col) =
                    make_float2(c[mt][nt][0] + b0, c[mt][nt][1] + b1);
                *(float2*)(C + (r0 + 8) * DD + col) =
                    make_float2(c[mt][nt][2] + b0, c[mt][nt][3] + b1);
            }
        }
    }
}

// ---------------- layer-2 GEMM: A pre-split bf16, 64-row tiles, 2 CTAs/SM ----------------
__global__ void __launch_bounds__(256, 2) k_mma2b(
    const __nv_bfloat16* __restrict__ Ah, const __nv_bfloat16* __restrict__ Al,
    const float* __restrict__ W, float* __restrict__ C, int Mtiles)
{
    extern __shared__ char smem[];
    char* sAh = smem;
    char* sAl = smem + A64_TILE;
    char* sWh = smem + 2 * A64_TILE;
    char* sWl = smem + 2 * A64_TILE + W128_TILE;
    const uint32_t uAh = (uint32_t)__cvta_generic_to_shared(sAh);
    const uint32_t uAl = (uint32_t)__cvta_generic_to_shared(sAl);
    const uint32_t uWh = (uint32_t)__cvta_generic_to_shared(sWh);
    const uint32_t uWl = (uint32_t)__cvta_generic_to_shared(sWl);

    const int t = threadIdx.x;
    const int L = t & 31;
    const int wid = t >> 5;
    const int wm = wid >> 2, wn = wid & 3;
    const int aRow  = wm * 32 + (L & 15);
    const int aHalf = (L >> 4) * 8;
    const int bRow  = wn * 32 + ((L >> 4) & 1) * 8 + (L & 7);
    const int bCol  = ((L >> 3) & 1) * 8;

    // W2 resident: split once
#pragma unroll
    for (int it = 0; it < 16; ++it) {
        int slot = it * 256 + t;
        int row = slot >> 5, c4 = (slot & 31) << 2;
        split_store(sWh, sWl, row, c4, *(const float4*)(W + (size_t)row * DD + c4));
    }

    float c[2][4][4];
    for (int tile = blockIdx.x; tile < Mtiles; tile += gridDim.x) {
        const size_t m0 = (size_t)tile * 64;
        __syncthreads();
#pragma unroll
        for (int it = 0; it < 8; ++it) {
            int slot = it * 256 + t;            // 0..2047
            int arr  = slot >> 10;              // 0=hi, 1=lo
            int row  = (slot >> 4) & 63;
            int c8   = slot & 15;
            const __nv_bfloat16* g = (arr ? Al : Ah) + (m0 + row) * DD + c8 * 8;
            char* dstBase = arr ? sAl : sAh;
            *(uint4*)(dstBase + (row * SP + c8 * 8) * 2) = *(const uint4*)g;
        }
        __syncthreads();

#pragma unroll
        for (int i = 0; i < 2; i++)
#pragma unroll
            for (int j = 0; j < 4; j++) {
                c[i][j][0] = 0.f; c[i][j][1] = 0.f; c[i][j][2] = 0.f; c[i][j][3] = 0.f;
            }
#pragma unroll
        for (int ks = 0; ks < 8; ++ks) {
            const int k0 = ks * 16;
            uint32_t ah[2][4], al[2][4], bh[2][4], bl[2][4];
#pragma unroll
            for (int mt = 0; mt < 2; ++mt) {
                uint32_t off = (uint32_t)(((aRow + mt * 16) * SP + k0 + aHalf) * 2);
                ldsm4(ah[mt][0], ah[mt][1], ah[mt][2], ah[mt][3], uAh + off);
                ldsm4(al[mt][0], al[mt][1], al[mt][2], al[mt][3], uAl + off);
            }
#pragma unroll
            for (int p = 0; p < 2; ++p) {
                uint32_t off = (uint32_t)(((bRow + p * 16) * SP + k0 + bCol) * 2);
                ldsm4(bh[p][0], bh[p][1], bh[p][2], bh[p][3], uWh + off);
                ldsm4(bl[p][0], bl[p][1], bl[p][2], bl[p][3], uWl + off);
            }
#pragma unroll
            for (int mt = 0; mt < 2; ++mt)
#pragma unroll
                for (int nt = 0; nt < 4; ++nt) {
                    const uint32_t bfh[2] = { bh[nt >> 1][(nt & 1) * 2],
                                              bh[nt >> 1][(nt & 1) * 2 + 1] };
                    const uint32_t bfl[2] = { bl[nt >> 1][(nt & 1) * 2],
                                              bl[nt >> 1][(nt & 1) * 2 + 1] };
                    mma16816(c[mt][nt], ah[mt], bfh);
                    mma16816(c[mt][nt], ah[mt], bfl);
                    mma16816(c[mt][nt], al[mt], bfh);
                }
        }

        const int lrow = L >> 2, lcol = (L & 3) * 2;
#pragma unroll
        for (int nt = 0; nt < 4; ++nt) {
            const int col = wn * 32 + nt * 8 + lcol;
#pragma unroll
            for (int mt = 0; mt < 2; ++mt) {
                size_t r0 = m0 + wm * 32 + mt * 16 + lrow;
                *(float2*)(C + r0 * DD + col)       = make_float2(c[mt][nt][0], c[mt][nt][1]);
                *(float2*)(C + (r0 + 8) * DD + col) = make_float2(c[mt][nt][2], c[mt][nt][3]);
            }
        }
    }
}

// ---------------- launch ----------------
extern "C" void kernel_launch(void* const* d_in, const int* in_sizes, int n_in,
                              void* d_out, int out_size) {
    const int*   tok = (const int*)d_in[0];
    const int*   ei  = (const int*)d_in[1];
    const float* emb = (const float*)d_in[2];
    const float* wn  = (const float*)d_in[3];
    const float* bn  = (const float*)d_in[4];
    const float* w1  = (const float*)d_in[5];
    const float* b1  = (const float*)d_in[6];
    const float* w2  = (const float*)d_in[7];
    const float* b2  = (const float*)d_in[8];
    float* out = (float*)d_out;

    const int* src = ei;
    const int* dst = ei + EE;

    float *t3p, *xbp, *wcp, *bcp;
    __nv_bfloat16 *h1hp, *h1lp;
    cudaGetSymbolAddress((void**)&t3p,  g_t3);
    cudaGetSymbolAddress((void**)&xbp,  g_xb);
    cudaGetSymbolAddress((void**)&wcp,  g_wc);
    cudaGetSymbolAddress((void**)&bcp,  g_bc);
    cudaGetSymbolAddress((void**)&h1hp, g_h1h);
    cudaGetSymbolAddress((void**)&h1lp, g_h1l);

    cudaFuncSetAttribute(k_mma_v, cudaFuncAttributeMaxDynamicSharedMemorySize, SMEM_G);
    cudaFuncSetAttribute(k_mma2b, cudaFuncAttributeMaxDynamicSharedMemorySize, SMEM_G);

    // side stream + fork/join events (created once; resources, not device memory)
    static cudaStream_t s2 = nullptr;
    static cudaEvent_t  evF = nullptr, evJ = nullptr;
    if (s2 == nullptr) {
        cudaStreamCreateWithFlags(&s2, cudaStreamNonBlocking);
        cudaEventCreateWithFlags(&evF, cudaEventDisableTiming);
        cudaEventCreateWithFlags(&evJ, cudaEventDisableTiming);
    }

    // ---- fork: CSR build (+merged tail outputs) on s2 ----
    cudaEventRecord(evF, 0);
    cudaStreamWaitEvent(s2, evF, 0);

    k_hist   <<<EE / 512, 256, 0, s2>>>((const int2*)dst);
    k_scan1  <<<NN / 1024, 1024, 0, s2>>>();
    k_scan23 <<<NN / 256, 256, 0, s2>>>(tok, out, (size_t)out_size);
    k_scatter<<<EE / 512, 256, 0, s2>>>((const int2*)src, (const int2*)dst);
    cudaEventRecord(evJ, s2);

    // ---- main stream: fold weights + vocab GEMM (independent of CSR) ----
    k_combine<<<DD, DIN>>>(w1, wn, bn);
    k_mma_v<<<296, 256, SMEM_G>>>(emb, wcp, bcp, t3p, VV / 64);

    // ---- join, then serial node-space chain ----
    cudaStreamWaitEvent(0, evJ, 0);

    k_agg0<<<(NN * 32) / 256, 256>>>(tok, t3p, b1);
    k_mma2b<<<296, 256, SMEM_G>>>(h1hp, h1lp, w2, xbp, NN / 64);
    k_agg2<<<(NN * 32) / 256, 256>>>(xbp, b2, out);
}

// round 16
// speedup vs baseline: 1.0655x; 1.0199x over previous
#include <cuda_runtime.h>
#include <cuda_bf16.h>
#include <cstdint>

#define NN  131072   // nodes
#define EE  524288   // edges
#define VV  32000    // vocab
#define DIN 256
#define DD  128
#define SP  136      // padded smem row stride (bf16 elems): conflict-free ldmatrix

// ---------------- device scratch (no allocations allowed) ----------------
__device__ float g_t3[(size_t)VV * DD];           // embed @ Wc^T + bc
__device__ __nv_bfloat16 g_h1h[(size_t)NN * DD];  // h1 hi (pre-split)
__device__ __nv_bfloat16 g_h1l[(size_t)NN * DD];  // h1 lo
__device__ float g_xb[(size_t)NN * DD];           // y2s = dinv .* (h1 @ W2^T)
__device__ float g_wc[DD * DIN];                  // Wc = W1 @ Wn
__device__ float g_bc[DD];                        // bc = W1 @ bn
__device__ int   g_cnt[NN];    // invariant: zero at call entry (re-zeroed in scan23)
__device__ float g_dinv[NN];
__device__ int   g_rowptr[NN + 1];
__device__ int   g_bsum[128];
__device__ int   g_col[EE];
__device__ int   g_slot[EE];   // per-edge slot within its dst row (captured in hist)

// ---------------- weight fold: Wc = W1 @ Wn,  bc = W1 @ bn ----------------
__global__ void k_combine(const float* __restrict__ w1, const float* __restrict__ wn,
                          const float* __restrict__ bn) {
    __shared__ float row[DD];
    int i = blockIdx.x;
    int j = threadIdx.x;
    if (j < DD) row[j] = w1[i * DD + j];
    __syncthreads();
    float acc = 0.f;
#pragma unroll 8
    for (int k = 0; k < DD; ++k) acc += row[k] * wn[k * DIN + j];
    g_wc[i * DIN + j] = acc;
    if (j == 0) {
        float b = 0.f;
        for (int k = 0; k < DD; ++k) b += row[k] * bn[k];
        g_bc[i] = b;
    }
}

// ---------------- CSR build ----------------
__global__ void k_hist(const int2* __restrict__ dst2) {   // 2 edges / thread
    int e2 = blockIdx.x * blockDim.x + threadIdx.x;
    if (e2 < EE / 2) {
        int2 d = dst2[e2];
        int s0 = atomicAdd(&g_cnt[d.x], 1);
        int s1 = atomicAdd(&g_cnt[d.y], 1);
        ((int2*)g_slot)[e2] = make_int2(s0, s1);
    }
}
__global__ void k_scan1() {
    __shared__ int wsum[32];
    int tid = threadIdx.x;
    int i = blockIdx.x * 1024 + tid;
    int lane = tid & 31, w = tid >> 5;
    int v = g_cnt[i];
    int x = v;
#pragma unroll
    for (int off = 1; off < 32; off <<= 1) {
        int y = __shfl_up_sync(0xFFFFFFFFu, x, off);
        if (lane >= off) x += y;
    }
    if (lane == 31) wsum[w] = x;
    __syncthreads();
    if (w == 0) {
        int s = wsum[lane];
#pragma unroll
        for (int off = 1; off < 32; off <<= 1) {
            int y = __shfl_up_sync(0xFFFFFFFFu, s, off);
            if (lane >= off) s += y;
        }
        wsum[lane] = s;
    }
    __syncthreads();
    int base = (w == 0) ? 0 : wsum[w - 1];
    g_rowptr[i] = base + x - v;
    if (tid == 1023) g_bsum[blockIdx.x] = base + x;
}
__global__ void k_scan23(const int* __restrict__ tok, float* __restrict__ out, size_t osz) {
    __shared__ int sb[128];
    int t = threadIdx.x;
    int i = blockIdx.x * 256 + t;
    if (t < 128) sb[t] = g_bsum[t];
    __syncthreads();
    for (int off = 1; off < 128; off <<= 1) {
        int v = 0;
        if (t < 128 && t >= off) v = sb[t - off];
        __syncthreads();
        if (t < 128) sb[t] += v;
        __syncthreads();
    }
    int grp = i >> 10;
    int off = (grp == 0) ? 0 : sb[grp - 1];
    g_rowptr[i] += off;
    g_dinv[i] = rsqrtf((float)(g_cnt[i] + 1));
    g_cnt[i]  = 0;
    if (i == 0) g_rowptr[NN] = EE;
    size_t base = (size_t)NN * DD;
    size_t ii = (size_t)i;
    if (base + (size_t)NN <= osz)     out[base + ii] = (float)tok[i];
    if (base + 2 * (size_t)NN <= osz) out[base + NN + ii] = 1.0f;
    if (base + 3 * (size_t)NN <= osz) out[base + 2 * (size_t)NN + ii] = (float)(i & 2047);
}
__global__ void k_scatter(const int2* __restrict__ src2, const int2* __restrict__ dst2) {
    int e2 = blockIdx.x * blockDim.x + threadIdx.x;
    if (e2 < EE / 2) {
        int2 d = dst2[e2];
        int2 s = src2[e2];
        int2 sl = ((const int2*)g_slot)[e2];
        g_col[g_rowptr[d.x] + sl.x] = s.x;
        g_col[g_rowptr[d.y] + sl.y] = s.y;
    }
}

// ---------------- layer-1 agg: h1 = relu(aggnorm(T3[tok]) + b1) -> split bf16 ----------------
__global__ void k_agg0(const int* __restrict__ tok, const float* __restrict__ t3,
                       const float* __restrict__ b1) {
    int gw   = (blockIdx.x * blockDim.x + threadIdx.x) >> 5;
    int lane = threadIdx.x & 31;
    if (gw >= NN) return;
    int beg = g_rowptr[gw], end = g_rowptr[gw + 1];
    float di = g_dinv[gw];
    const float4* x4 = (const float4*)t3;
    float4 v = x4[(size_t)tok[gw] * 32 + lane];
    float s = di * di;
    float ax = v.x * s, ay = v.y * s, az = v.z * s, aw = v.w * s;
    for (int j = beg; j < end; ++j) {
        int   sc = g_col[j];
        float w  = g_dinv[sc] * di;
        float4 u = x4[(size_t)tok[sc] * 32 + lane];
        ax += w * u.x; ay += w * u.y; az += w * u.z; aw += w * u.w;
    }
    float4 b = ((const float4*)b1)[lane];
    float ox = fmaxf(ax + b.x, 0.f), oy = fmaxf(ay + b.y, 0.f);
    float oz = fmaxf(az + b.z, 0.f), ow = fmaxf(aw + b.w, 0.f);
    __nv_bfloat16 hx = __float2bfloat16(ox), hy = __float2bfloat16(oy);
    __nv_bfloat16 hz = __float2bfloat16(oz), hw = __float2bfloat16(ow);
    __nv_bfloat16 lx = __float2bfloat16(ox - __bfloat162float(hx));
    __nv_bfloat16 ly = __float2bfloat16(oy - __bfloat162float(hy));
    __nv_bfloat16 lz = __float2bfloat16(oz - __bfloat162float(hz));
    __nv_bfloat16 lw = __float2bfloat16(ow - __bfloat162float(hw));
    size_t o2 = (size_t)gw * 64 + lane * 2;
    ((__nv_bfloat162*)g_h1h)[o2]     = __halves2bfloat162(hx, hy);
    ((__nv_bfloat162*)g_h1h)[o2 + 1] = __halves2bfloat162(hz, hw);
    ((__nv_bfloat162*)g_h1l)[o2]     = __halves2bfloat162(lx, ly);
    ((__nv_bfloat162*)g_h1l)[o2 + 1] = __halves2bfloat162(lz, lw);
}

// ---------------- layer-2 aggregation on pre-scaled rows ----------------
// x holds y2s = dinv .* y2 ; out = dinv[d] * (y2s[d] + sum_e y2s[src]) + b2
__global__ void k_agg2(const float* __restrict__ x, const float* __restrict__ b2,
                       float* __restrict__ outp) {
    int gw   = (blockIdx.x * blockDim.x + threadIdx.x) >> 5;
    int lane = threadIdx.x & 31;
    if (gw >= NN) return;
    int beg = g_rowptr[gw], end = g_rowptr[gw + 1];
    float di = g_dinv[gw];
    const float4* x4 = (const float4*)x;
    float4 v = x4[(size_t)gw * 32 + lane];
    float ax = v.x, ay = v.y, az = v.z, aw = v.w;
    for (int j = beg; j < end; ++j) {
        int sc = g_col[j];
        float4 u = x4[(size_t)sc * 32 + lane];
        ax += u.x; ay += u.y; az += u.z; aw += u.w;
    }
    float4 b = ((const float4*)b2)[lane];
    ((float4*)outp)[(size_t)gw * 32 + lane] =
        make_float4(di * ax + b.x, di * ay + b.y, di * az + b.z, di * aw + b.w);
}

// ---------------- HMMA helpers ----------------
__device__ __forceinline__ void split_store(char* hi, char* lo, int row, int c4, float4 f) {
    __nv_bfloat16 hx = __float2bfloat16(f.x), hy = __float2bfloat16(f.y);
    __nv_bfloat16 hz = __float2bfloat16(f.z), hw = __float2bfloat16(f.w);
    __nv_bfloat16 lx = __float2bfloat16(f.x - __bfloat162float(hx));
    __nv_bfloat16 ly = __float2bfloat16(f.y - __bfloat162float(hy));
    __nv_bfloat16 lz = __float2bfloat16(f.z - __bfloat162float(hz));
    __nv_bfloat16 lw = __float2bfloat16(f.w - __bfloat162float(hw));
    size_t off = ((size_t)row * SP + c4) * 2;
    *(__nv_bfloat162*)(hi + off)     = __halves2bfloat162(hx, hy);
    *(__nv_bfloat162*)(hi + off + 4) = __halves2bfloat162(hz, hw);
    *(__nv_bfloat162*)(lo + off)     = __halves2bfloat162(lx, ly);
    *(__nv_bfloat162*)(lo + off + 4) = __halves2bfloat162(lz, lw);
}
__device__ __forceinline__ void ldsm4(uint32_t& r0, uint32_t& r1, uint32_t& r2, uint32_t& r3,
                                      uint32_t addr) {
    asm volatile("ldmatrix.sync.aligned.m8n8.x4.shared.b16 {%0,%1,%2,%3}, [%4];"
                 : "=r"(r0), "=r"(r1), "=r"(r2), "=r"(r3) : "r"(addr));
}
__device__ __forceinline__ void mma16816(float* c, const uint32_t* a, const uint32_t* b) {
    asm volatile(
        "mma.sync.aligned.m16n8k16.row.col.f32.bf16.bf16.f32 "
        "{%0,%1,%2,%3}, {%4,%5,%6,%7}, {%8,%9}, {%0,%1,%2,%3};"
        : "+f"(c[0]), "+f"(c[1]), "+f"(c[2]), "+f"(c[3])
        : "r"(a[0]), "r"(a[1]), "r"(a[2]), "r"(a[3]), "r"(b[0]), "r"(b[1]));
}

#define A64_TILE  (64  * SP * 2)   // 17408
#define W128_TILE (128 * SP * 2)   // 34816
#define SMEM_G (2 * A64_TILE + 2 * W128_TILE)   // 104448 -> 2 CTAs/SM

// ---------------- vocab GEMM: 64-row tiles, 2 CTAs/SM, fp32 A split in-kernel ----------------
__global__ void __launch_bounds__(256, 2) k_mma_v(
    const float* __restrict__ A, const float* __restrict__ W,
    const float* __restrict__ bias, float* __restrict__ C, int Mtiles)
{
    extern __shared__ char smem[];
    char* sAh = smem;
    char* sAl = smem + A64_TILE;
    char* sWh = smem + 2 * A64_TILE;
    char* sWl = smem + 2 * A64_TILE + W128_TILE;
    const uint32_t uAh = (uint32_t)__cvta_generic_to_shared(sAh);
    const uint32_t uAl = (uint32_t)__cvta_generic_to_shared(sAl);
    const uint32_t uWh = (uint32_t)__cvta_generic_to_shared(sWh);
    const uint32_t uWl = (uint32_t)__cvta_generic_to_shared(sWl);

    const int t = threadIdx.x;
    const int L = t & 31;
    const int wid = t >> 5;
    const int wm = wid >> 2, wn = wid & 3;
    const int aRow  = wm * 32 + (L & 15);
    const int aHalf = (L >> 4) * 8;
    const int bRow  = wn * 32 + ((L >> 4) & 1) * 8 + (L & 7);
    const int bCol  = ((L >> 3) & 1) * 8;

    float c[2][4][4];
    for (int tile = blockIdx.x; tile < Mtiles; tile += gridDim.x) {
        const size_t m0 = (size_t)tile * 64;
#pragma unroll
        for (int i = 0; i < 2; i++)
#pragma unroll
            for (int j = 0; j < 4; j++) {
                c[i][j][0] = 0.f; c[i][j][1] = 0.f; c[i][j][2] = 0.f; c[i][j][3] = 0.f;
            }

        for (int kb = 0; kb < DIN; kb += 128) {
            __syncthreads();
#pragma unroll
            for (int it = 0; it < 8; ++it) {
                int slot = it * 256 + t;
                int row = slot >> 5, c4 = (slot & 31) << 2;
                split_store(sAh, sAl, row, c4,
                            *(const float4*)(A + (m0 + row) * DIN + kb + c4));
            }
#pragma unroll
            for (int it = 0; it < 16; ++it) {
                int slot = it * 256 + t;
                int row = slot >> 5, c4 = (slot & 31) << 2;
                split_store(sWh, sWl, row, c4,
                            *(const float4*)(W + (size_t)row * DIN + kb + c4));
            }
            __syncthreads();

#pragma unroll
            for (int ks = 0; ks < 8; ++ks) {
                const int k0 = ks * 16;
                uint32_t ah[2][4], al[2][4], bh[2][4], bl[2][4];
#pragma unroll
                for (int mt = 0; mt < 2; ++mt) {
                    uint32_t off = (uint32_t)(((aRow + mt * 16) * SP + k0 + aHalf) * 2);
                    ldsm4(ah[mt][0], ah[mt][1], ah[mt][2], ah[mt][3], uAh + off);
                    ldsm4(al[mt][0], al[mt][1], al[mt][2], al[mt][3], uAl + off);
                }
#pragma unroll
                for (int p = 0; p < 2; ++p) {
                    uint32_t off = (uint32_t)(((bRow + p * 16) * SP + k0 + bCol) * 2);
                    ldsm4(bh[p][0], bh[p][1], bh[p][2], bh[p][3], uWh + off);
                    ldsm4(bl[p][0], bl[p][1], bl[p][2], bl[p][3], uWl + off);
                }
#pragma unroll
                for (int mt = 0; mt < 2; ++mt)
#pragma unroll
                    for (int nt = 0; nt < 4; ++nt) {
                        const uint32_t bfh[2] = { bh[nt >> 1][(nt & 1) * 2],
                                                  bh[nt >> 1][(nt & 1) * 2 + 1] };
                        const uint32_t bfl[2] = { bl[nt >> 1][(nt & 1) * 2],
                                                  bl[nt >> 1][(nt & 1) * 2 + 1] };
                        mma16816(c[mt][nt], ah[mt], bfh);
                        mma16816(c[mt][nt], ah[mt], bfl);
                        mma16816(c[mt][nt], al[mt], bfh);
                    }
            }
        }

        const int lrow = L >> 2, lcol = (L & 3) * 2;
#pragma unroll
        for (int nt = 0; nt < 4; ++nt) {
            const int col = wn * 32 + nt * 8 + lcol;
            float b0 = __ldg(bias + col), b1 = __ldg(bias + col + 1);
#pragma unroll
            for (int mt = 0; mt < 2; ++mt) {
                size_t r0 = m0 + wm * 32 + mt * 16 + lrow;
                *(float2*)(C + r0 * DD + col) =
                    make_float2(c[mt][nt][0] + b0, c[mt][nt][1] + b1);
                *(float2*)(C + (r0 + 8) * DD + col) =
                    make_float2(c[mt][nt][2] + b0, c[mt][nt][3] + b1);
            }
        }
    }
}

// ---------------- layer-2 GEMM: A pre-split bf16; epilogue scales rows by dinv ----------------
__global__ void __launch_bounds__(256, 2) k_mma2b(
    const __nv_bfloat16* __restrict__ Ah, const __nv_bfloat16* __restrict__ Al,
    const float* __restrict__ W, float* __restrict__ C, int Mtiles)
{
    extern __shared__ char smem[];
    char* sAh = smem;
    char* sAl = smem + A64_TILE;
    char* sWh = smem + 2 * A64_TILE;
    char* sWl = smem + 2 * A64_TILE + W128_TILE;
    const uint32_t uAh = (uint32_t)__cvta_generic_to_shared(sAh);
    const uint32_t uAl = (uint32_t)__cvta_generic_to_shared(sAl);
    const uint32_t uWh = (uint32_t)__cvta_generic_to_shared(sWh);
    const uint32_t uWl = (uint32_t)__cvta_generic_to_shared(sWl);

    const int t = threadIdx.x;
    const int L = t & 31;
    const int wid = t >> 5;
    const int wm = wid >> 2, wn = wid & 3;
    const int aRow  = wm * 32 + (L & 15);
    const int aHalf = (L >> 4) * 8;
    const int bRow  = wn * 32 + ((L >> 4) & 1) * 8 + (L & 7);
    const int bCol  = ((L >> 3) & 1) * 8;

    // W2 resident: split once
#pragma unroll
    for (int it = 0; it < 16; ++it) {
        int slot = it * 256 + t;
        int row = slot >> 5, c4 = (slot & 31) << 2;
        split_store(sWh, sWl, row, c4, *(const float4*)(W + (size_t)row * DD + c4));
    }

    float c[2][4][4];
    for (int tile = blockIdx.x; tile < Mtiles; tile += gridDim.x) {
        const size_t m0 = (size_t)tile * 64;
        __syncthreads();
#pragma unroll
        for (int it = 0; it < 8; ++it) {
            int slot = it * 256 + t;
            int arr  = slot >> 10;
            int row  = (slot >> 4) & 63;
            int c8   = slot & 15;
            const __nv_bfloat16* g = (arr ? Al : Ah) + (m0 + row) * DD + c8 * 8;
            char* dstBase = arr ? sAl : sAh;
            *(uint4*)(dstBase + (row * SP + c8 * 8) * 2) = *(const uint4*)g;
        }
        __syncthreads();

#pragma unroll
        for (int i = 0; i < 2; i++)
#pragma unroll
            for (int j = 0; j < 4; j++) {
                c[i][j][0] = 0.f; c[i][j][1] = 0.f; c[i][j][2] = 0.f; c[i][j][3] = 0.f;
            }
#pragma unroll
        for (int ks = 0; ks < 8; ++ks) {
            const int k0 = ks * 16;
            uint32_t ah[2][4], al[2][4], bh[2][4], bl[2][4];
#pragma unroll
            for (int mt = 0; mt < 2; ++mt) {
                uint32_t off = (uint32_t)(((aRow + mt * 16) * SP + k0 + aHalf) * 2);
                ldsm4(ah[mt][0], ah[mt][1], ah[mt][2], ah[mt][3], uAh + off);
                ldsm4(al[mt][0], al[mt][1], al[mt][2], al[mt][3], uAl + off);
            }
#pragma unroll
            for (int p = 0; p < 2; ++p) {
                uint32_t off = (uint32_t)(((bRow + p * 16) * SP + k0 + bCol) * 2);
                ldsm4(bh[p][0], bh[p][1], bh[p][2], bh[p][3], uWh + off);
                ldsm4(bl[p][0], bl[p][1], bl[p][2], bl[p][3], uWl + off);
            }
#pragma unroll
            for (int mt = 0; mt < 2; ++mt)
#pragma unroll
                for (int nt = 0; nt < 4; ++nt) {
                    const uint32_t bfh[2] = { bh[nt >> 1][(nt & 1) * 2],
                                              bh[nt >> 1][(nt & 1) * 2 + 1] };
                    const uint32_t bfl[2] = { bl[nt >> 1][(nt & 1) * 2],
                                              bl[nt >> 1][(nt & 1) * 2 + 1] };
                    mma16816(c[mt][nt], ah[mt], bfh);
                    mma16816(c[mt][nt], ah[mt], bfl);
                    mma16816(c[mt][nt], al[mt], bfh);
                }
        }

        const int lrow = L >> 2, lcol = (L & 3) * 2;
#pragma unroll
        for (int mt = 0; mt < 2; ++mt) {
            size_t r0 = m0 + wm * 32 + mt * 16 + lrow;
            float d0 = g_dinv[r0];
            float d1 = g_dinv[r0 + 8];
#pragma unroll
            for (int nt = 0; nt < 4; ++nt) {
                const int col = wn * 32 + nt * 8 + lcol;
                *(float2*)(C + r0 * DD + col) =
                    make_float2(d0 * c[mt][nt][0], d0 * c[mt][nt][1]);
                *(float2*)(C + (r0 + 8) * DD + col) =
                    make_float2(d1 * c[mt][nt][2], d1 * c[mt][nt][3]);
            }
        }
    }
}

// ---------------- launch ----------------
extern "C" void kernel_launch(void* const* d_in, const int* in_sizes, int n_in,
                              void* d_out, int out_size) {
    const int*   tok = (const int*)d_in[0];
    const int*   ei  = (const int*)d_in[1];
    const float* emb = (const float*)d_in[2];
    const float* wn  = (const float*)d_in[3];
    const float* bn  = (const float*)d_in[4];
    const float* w1  = (const float*)d_in[5];
    const float* b1  = (const float*)d_in[6];
    const float* w2  = (const float*)d_in[7];
    const float* b2  = (const float*)d_in[8];
    float* out = (float*)d_out;

    const int* src = ei;
    const int* dst = ei + EE;

    float *t3p, *xbp, *wcp, *bcp;
    __nv_bfloat16 *h1hp, *h1lp;
    cudaGetSymbolAddress((void**)&t3p,  g_t3);
    cudaGetSymbolAddress((void**)&xbp,  g_xb);
    cudaGetSymbolAddress((void**)&wcp,  g_wc);
    cudaGetSymbolAddress((void**)&bcp,  g_bc);
    cudaGetSymbolAddress((void**)&h1hp, g_h1h);
    cudaGetSymbolAddress((void**)&h1lp, g_h1l);

    cudaFuncSetAttribute(k_mma_v, cudaFuncAttributeMaxDynamicSharedMemorySize, SMEM_G);
    cudaFuncSetAttribute(k_mma2b, cudaFuncAttributeMaxDynamicSharedMemorySize, SMEM_G);

    // side stream + fork/join events (created once; resources, not device memory)
    static cudaStream_t s2 = nullptr;
    static cudaEvent_t  evF = nullptr, evJ = nullptr;
    if (s2 == nullptr) {
        cudaStreamCreateWithFlags(&s2, cudaStreamNonBlocking);
        cudaEventCreateWithFlags(&evF, cudaEventDisableTiming);
        cudaEventCreateWithFlags(&evJ, cudaEventDisableTiming);
    }

    // ---- fork: CSR build (+merged tail outputs) on s2 ----
    cudaEventRecord(evF, 0);
    cudaStreamWaitEvent(s2, evF, 0);

    k_hist   <<<EE / 512, 256, 0, s2>>>((const int2*)dst);
    k_scan1  <<<NN / 1024, 1024, 0, s2>>>();
    k_scan23 <<<NN / 256, 256, 0, s2>>>(tok, out, (size_t)out_size);
    k_scatter<<<EE / 512, 256, 0, s2>>>((const int2*)src, (const int2*)dst);
    cudaEventRecord(evJ, s2);

    // ---- main stream: fold weights + vocab GEMM (independent of CSR) ----
    k_combine<<<DD, DIN>>>(w1, wn, bn);
    k_mma_v<<<296, 256, SMEM_G>>>(emb, wcp, bcp, t3p, VV / 64);

    // ---- join, then serial node-space chain ----
    cudaStreamWaitEvent(0, evJ, 0);

    k_agg0<<<(NN * 32) / 256, 256>>>(tok, t3p, b1);
    k_mma2b<<<296, 256, SMEM_G>>>(h1hp, h1lp, w2, xbp, NN / 64);
    k_agg2<<<(NN * 32) / 256, 256>>>(xbp, b2, out);
}